// round 3
// baseline (speedup 1.0000x reference)
#include <cuda_runtime.h>
#include <math.h>

// Problem constants
#define BB 64
#define NN 1080
#define FF 512
#define S1 360
#define H1 784
#define S2 120
#define H2 28

// Scratch (device globals)
__device__ float g_part[4][S1 * FF];  // 4 batch-group partials of nodeconv(batch-sum)
__device__ float g_h1row[S1 * H1];    // gelu(360*hsum1@W1 + b1)  [360,784]

__device__ __forceinline__ float gelu_f(float v) {
    return 0.5f * v * (1.0f + erff(v * 0.70710678118654752440f));
}

// ---------------------------------------------------------------------------
// K1: part[g][s,f] = sum_{b in group g (16)} sum_p x[b,3s+p,f] * nc1_w[p,f]
// The ONLY pass over the 141.5MB input. grid (180, 4) x 256 = 720 blocks.
// ---------------------------------------------------------------------------
__global__ __launch_bounds__(256) void k_fuse1(const float4* __restrict__ x,
                                               const float4* __restrict__ w1) {
    int i = blockIdx.x * 256 + threadIdx.x;      // 0 .. 46079  (= 360*128)
    int f4 = i & 127;
    int s  = i >> 7;
    float4 w0 = w1[f4], wa = w1[128 + f4], wb = w1[256 + f4];
    const float4* base = x + (size_t)(3 * s) * 128 + f4;
    int b0 = blockIdx.y * 16;
    float4 acc = make_float4(0.f, 0.f, 0.f, 0.f);
#pragma unroll 4
    for (int b = b0; b < b0 + 16; b++) {
        const float4* p = base + (size_t)b * (NN * FF / 4);
        float4 v0 = __ldg(p);
        float4 v1 = __ldg(p + 128);
        float4 v2 = __ldg(p + 256);
        acc.x += v0.x * w0.x + v1.x * wa.x + v2.x * wb.x;
        acc.y += v0.y * w0.y + v1.y * wa.y + v2.y * wb.y;
        acc.z += v0.z * w0.z + v1.z * wa.z + v2.z * wb.z;
        acc.w += v0.w * w0.w + v1.w * wa.w + v2.w * wb.w;
    }
    reinterpret_cast<float4*>(g_part[blockIdx.y])[i] = acc;
}

// ---------------------------------------------------------------------------
// K2: h1row = gelu(360*(hsum1 @ prop1_W) + b1).  M=360 N=784 K=512.
// Tiles: BM=72 x BN=28 -> grid (28,5)=140 blocks (perfect wave on 148 SMs).
// 128 threads, 126 compute a 4x4 micro-tile each. BK=32, double buffered.
// A is materialized on the fly as the sum of the 4 fuse1 partials (L2 hits).
// ---------------------------------------------------------------------------
__global__ __launch_bounds__(128) void k_gemm1(const float* __restrict__ Wp,
                                               const float* __restrict__ bias) {
    __shared__ float  As[2][32][73];   // padded: conflict-free transpose store
    __shared__ float4 Bs[2][32][7];

    const int tid = threadIdx.x;
    const int row_base = blockIdx.y * 72;   // 5*72 = 360 exact
    const int col0 = blockIdx.x * 28;       // 28*28 = 784 exact
    const int ty = tid / 7, tx = tid % 7;   // compute coords (ty<18 when tid<126)
    const bool active = tid < 126;

    const float4* P0 = (const float4*)g_part[0];
    const float4* P1 = (const float4*)g_part[1];
    const float4* P2 = (const float4*)g_part[2];
    const float4* P3 = (const float4*)g_part[3];

    float4 ra[5];
    float4 rb[2];
    float acc[4][4] = {};

#define LOAD_TILE(K0)                                                          \
    {                                                                          \
        _Pragma("unroll")                                                      \
        for (int it = 0; it < 5; it++) {                                       \
            int idx = tid + it * 128;                                          \
            if (idx < 576) {                                                   \
                int r = idx >> 3, kq = idx & 7;                                \
                int g = (row_base + r) * 128 + ((K0) >> 2) + kq;               \
                float4 a = P0[g], b = P1[g], c = P2[g], d = P3[g];             \
                ra[it] = make_float4((a.x + b.x) + (c.x + d.x),                \
                                     (a.y + b.y) + (c.y + d.y),                \
                                     (a.z + b.z) + (c.z + d.z),                \
                                     (a.w + b.w) + (c.w + d.w));               \
            }                                                                  \
        }                                                                      \
        _Pragma("unroll")                                                      \
        for (int it = 0; it < 2; it++) {                                       \
            int idx = tid + it * 128;                                          \
            if (idx < 224) {                                                   \
                int kr = idx / 7, cq = idx % 7;                                \
                rb[it] = ((const float4*)(Wp + ((K0) + kr) * H1 + col0))[cq];  \
            }                                                                  \
        }                                                                      \
    }

#define STORE_TILE(BUF)                                                        \
    {                                                                          \
        _Pragma("unroll")                                                      \
        for (int it = 0; it < 5; it++) {                                       \
            int idx = tid + it * 128;                                          \
            if (idx < 576) {                                                   \
                int r = idx >> 3, kq = idx & 7;                                \
                As[BUF][kq * 4 + 0][r] = ra[it].x;                             \
                As[BUF][kq * 4 + 1][r] = ra[it].y;                             \
                As[BUF][kq * 4 + 2][r] = ra[it].z;                             \
                As[BUF][kq * 4 + 3][r] = ra[it].w;                             \
            }                                                                  \
        }                                                                      \
        _Pragma("unroll")                                                      \
        for (int it = 0; it < 2; it++) {                                       \
            int idx = tid + it * 128;                                          \
            if (idx < 224) { Bs[BUF][idx / 7][idx % 7] = rb[it]; }             \
        }                                                                      \
    }

    LOAD_TILE(0);
    STORE_TILE(0);
    __syncthreads();

    for (int kt = 0; kt < 16; kt++) {
        int cur = kt & 1;
        if (kt < 15) LOAD_TILE((kt + 1) * 32);
        if (active) {
#pragma unroll
            for (int kk = 0; kk < 32; kk++) {
                float a0 = As[cur][kk][ty * 4 + 0];
                float a1 = As[cur][kk][ty * 4 + 1];
                float a2 = As[cur][kk][ty * 4 + 2];
                float a3 = As[cur][kk][ty * 4 + 3];
                float4 b = Bs[cur][kk][tx];
                acc[0][0] += a0 * b.x; acc[0][1] += a0 * b.y; acc[0][2] += a0 * b.z; acc[0][3] += a0 * b.w;
                acc[1][0] += a1 * b.x; acc[1][1] += a1 * b.y; acc[1][2] += a1 * b.z; acc[1][3] += a1 * b.w;
                acc[2][0] += a2 * b.x; acc[2][1] += a2 * b.y; acc[2][2] += a2 * b.z; acc[2][3] += a2 * b.w;
                acc[3][0] += a3 * b.x; acc[3][1] += a3 * b.y; acc[3][2] += a3 * b.z; acc[3][3] += a3 * b.w;
            }
        }
        if (kt < 15) {
            STORE_TILE(cur ^ 1);
            __syncthreads();
        }
    }

    if (active) {
        int cb = col0 + tx * 4;
        float b0 = bias[cb + 0], b1 = bias[cb + 1], b2 = bias[cb + 2], b3 = bias[cb + 3];
#pragma unroll
        for (int i = 0; i < 4; i++) {
            int row = row_base + ty * 4 + i;
            float4 o;
            o.x = gelu_f(360.0f * acc[i][0] + b0);
            o.y = gelu_f(360.0f * acc[i][1] + b1);
            o.z = gelu_f(360.0f * acc[i][2] + b2);
            o.w = gelu_f(360.0f * acc[i][3] + b3);
            *(float4*)&g_h1row[row * H1 + cb] = o;
        }
    }
#undef LOAD_TILE
#undef STORE_TILE
}

// ---------------------------------------------------------------------------
// K3: full tail. grid = 40 blocks (one per classifier row r), 256 threads.
//   hsum2 (node-conv-2, x64 batch factor) -> gemm2+gelu -> cls1+gelu -> cls2
//   -> broadcast [40,10] block x64 into output [2560,10].
// prop2_W staged in dynamic smem (88KB).
// ---------------------------------------------------------------------------
__global__ __launch_bounds__(256) void k_tail(const float* __restrict__ W2,
                                              const float* __restrict__ b2p,
                                              const float* __restrict__ nc2w,
                                              const float* __restrict__ cw1,
                                              const float* __restrict__ cb1,
                                              const float* __restrict__ cw2,
                                              const float* __restrict__ cb2,
                                              float* __restrict__ out) {
    extern __shared__ float dynsm[];
    float* sW2 = dynsm;               // 784*28 = 21952 floats
    float* hs2 = dynsm + 21952;       // 3*784  = 2352 floats
    __shared__ float part[252];
    __shared__ float o2[84];
    __shared__ float hc[32];
    __shared__ float orow[10];

    const int r = blockIdx.x;
    const int tid = threadIdx.x;

    // stage prop2_W into smem
    const float4* W4 = (const float4*)W2;
    for (int i = tid; i < (H1 * H2) / 4; i += 256) ((float4*)sW2)[i] = W4[i];

    // hsum2 rows for s = 3r .. 3r+2 (uses h1row rows 9r .. 9r+8)
    for (int j = tid; j < 3 * H1; j += 256) {
        int sl = j / H1, f = j - sl * H1;
        int rowg = 9 * r + 3 * sl;
        float a = 0.f;
#pragma unroll
        for (int p = 0; p < 3; p++)
            a += g_h1row[(rowg + p) * H1 + f] * nc2w[p * H1 + f];
        hs2[j] = 64.0f * a;
    }
    __syncthreads();

    // gemm2: 84 outputs, 3 k-chunks each
    if (tid < 252) {
        int o = tid % 84, kg = tid / 84;
        int sl = o / 28, c = o - sl * 28;
        int k0 = kg * 262;
        int k1 = (kg == 2) ? H1 : k0 + 262;
        const float* hrow = hs2 + sl * H1;
        float a = 0.f;
        for (int k = k0; k < k1; k++) a += hrow[k] * sW2[k * H2 + c];
        part[kg * 84 + o] = a;
    }
    __syncthreads();
    if (tid < 84) {
        float s = part[tid] + part[84 + tid] + part[168 + tid];
        o2[tid] = gelu_f(120.0f * s + b2p[tid % 28]);
    }
    __syncthreads();

    // classifier layer 1: hc[j] = gelu(o2 . cw1[:,j] + cb1[j])
    if (tid < 32) {
        float a = cb1[tid];
#pragma unroll 4
        for (int k = 0; k < 84; k++) a += o2[k] * cw1[k * 32 + tid];
        hc[tid] = gelu_f(a);
    }
    __syncthreads();

    // classifier layer 2
    if (tid < 10) {
        float a = cb2[tid];
#pragma unroll
        for (int k = 0; k < 32; k++) a += hc[k] * cw2[k * 10 + tid];
        orow[tid] = a;
    }
    __syncthreads();

    // broadcast into output: out[(b*40 + r)*10 + c] for b = 0..63
    for (int i = tid; i < 640; i += 256) {
        int b = i / 10, c = i - b * 10;
        out[b * 400 + r * 10 + c] = orow[c];
    }
}

extern "C" void kernel_launch(void* const* d_in, const int* in_sizes, int n_in,
                              void* d_out, int out_size) {
    (void)in_sizes; (void)n_in; (void)out_size;
    const float* x       = (const float*)d_in[0];
    const float* nc1_w   = (const float*)d_in[1];
    // d_in[2]=gap1_w, d_in[3]=gap1_b : adjacency collapses to ~I -> irrelevant
    const float* prop1_W = (const float*)d_in[4];
    const float* prop1_b = (const float*)d_in[5];
    const float* nc2_w   = (const float*)d_in[6];
    // d_in[7]=gap2_w, d_in[8]=gap2_b : irrelevant
    const float* prop2_W = (const float*)d_in[9];
    const float* prop2_b = (const float*)d_in[10];
    const float* cls_w1  = (const float*)d_in[11];
    const float* cls_b1  = (const float*)d_in[12];
    const float* cls_w2  = (const float*)d_in[13];
    const float* cls_b2  = (const float*)d_in[14];
    float* out = (float*)d_out;

    // idempotent, host-side, not a stream op: safe under capture
    cudaFuncSetAttribute(k_tail, cudaFuncAttributeMaxDynamicSharedMemorySize, 98304);

    k_fuse1<<<dim3(180, 4), 256>>>((const float4*)x, (const float4*)nc1_w);
    k_gemm1<<<dim3(28, 5), 128>>>(prop1_W, prop1_b);
    k_tail<<<40, 256, (21952 + 2352) * sizeof(float)>>>(
        prop2_W, prop2_b, nc2_w, cls_w1, cls_b1, cls_w2, cls_b2, out);
}

// round 4
// speedup vs baseline: 1.1995x; 1.1995x over previous
#include <cuda_runtime.h>
#include <math.h>

// Problem constants
#define BB 64
#define NN 1080
#define FF 512
#define S1 360
#define H1 784
#define S2 120
#define H2 28

// Scratch (device globals)
__device__ float g_part[8][S1 * FF];  // 8 batch-group partials of nodeconv(batch-sum)
__device__ float g_hsum1[S1 * FF];    // reduced: nodeconv(full batch-sum)  [360,512]
__device__ float g_h1row[S1 * H1];    // gelu(360*hsum1@W1 + b1)           [360,784]

__device__ __forceinline__ float gelu_f(float v) {
    return 0.5f * v * (1.0f + erff(v * 0.70710678118654752440f));
}

// ---------------------------------------------------------------------------
// K1: part[g][s,f] = sum_{b in group g (8 batches)} sum_p x[b,3s+p,f]*nc1_w[p,f]
// The ONLY pass over the 141.5MB input. grid (180, 8) x 256 = 1440 blocks.
// ---------------------------------------------------------------------------
__global__ __launch_bounds__(256) void k_fuse1(const float4* __restrict__ x,
                                               const float4* __restrict__ w1) {
    int i = blockIdx.x * 256 + threadIdx.x;      // 0 .. 46079  (= 360*128)
    int f4 = i & 127;
    int s  = i >> 7;
    float4 w0 = w1[f4], wa = w1[128 + f4], wb = w1[256 + f4];
    const float4* base = x + (size_t)(3 * s) * 128 + f4;
    int b0 = blockIdx.y * 8;
    float4 acc = make_float4(0.f, 0.f, 0.f, 0.f);
#pragma unroll
    for (int b = b0; b < b0 + 8; b++) {
        const float4* p = base + (size_t)b * (NN * FF / 4);
        float4 v0 = __ldg(p);
        float4 v1 = __ldg(p + 128);
        float4 v2 = __ldg(p + 256);
        acc.x += v0.x * w0.x + v1.x * wa.x + v2.x * wb.x;
        acc.y += v0.y * w0.y + v1.y * wa.y + v2.y * wb.y;
        acc.z += v0.z * w0.z + v1.z * wa.z + v2.z * wb.z;
        acc.w += v0.w * w0.w + v1.w * wa.w + v2.w * wb.w;
    }
    reinterpret_cast<float4*>(g_part[blockIdx.y])[i] = acc;
}

// ---------------------------------------------------------------------------
// K1b: g_hsum1 = sum of the 8 partials. 180 blocks x 256. L2-resident, ~2us.
// ---------------------------------------------------------------------------
__global__ __launch_bounds__(256) void k_reduce() {
    int i = blockIdx.x * 256 + threadIdx.x;      // 0 .. 46079 (float4)
    float4 s = make_float4(0.f, 0.f, 0.f, 0.f);
#pragma unroll
    for (int g = 0; g < 8; g++) {
        float4 v = reinterpret_cast<const float4*>(g_part[g])[i];
        s.x += v.x; s.y += v.y; s.z += v.z; s.w += v.w;
    }
    reinterpret_cast<float4*>(g_hsum1)[i] = s;
}

// ---------------------------------------------------------------------------
// K2: h1row = gelu(360*(hsum1 @ prop1_W) + b1).  M=360 N=784 K=512.
// Tiles: BM=72 x BN=28 -> grid (28,5)=140 blocks (perfect wave on 148 SMs).
// 128 threads, 126 compute a 4x4 micro-tile each. BK=32, double buffered.
// ---------------------------------------------------------------------------
__global__ __launch_bounds__(128) void k_gemm1(const float* __restrict__ Wp,
                                               const float* __restrict__ bias) {
    __shared__ float  As[2][32][73];   // padded: conflict-free transpose store
    __shared__ float4 Bs[2][32][7];

    const int tid = threadIdx.x;
    const int row_base = blockIdx.y * 72;   // 5*72 = 360 exact
    const int col0 = blockIdx.x * 28;       // 28*28 = 784 exact
    const int ty = tid / 7, tx = tid % 7;   // compute coords (ty<18 when tid<126)
    const bool active = tid < 126;

    const float4* A4 = (const float4*)g_hsum1;

    float4 ra[5];
    float4 rb[2];
    float acc[4][4] = {};

#define LOAD_TILE(K0)                                                          \
    {                                                                          \
        _Pragma("unroll")                                                      \
        for (int it = 0; it < 5; it++) {                                       \
            int idx = tid + it * 128;                                          \
            if (idx < 576) {                                                   \
                int r = idx >> 3, kq = idx & 7;                                \
                ra[it] = A4[(row_base + r) * 128 + ((K0) >> 2) + kq];          \
            }                                                                  \
        }                                                                      \
        _Pragma("unroll")                                                      \
        for (int it = 0; it < 2; it++) {                                       \
            int idx = tid + it * 128;                                          \
            if (idx < 224) {                                                   \
                int kr = idx / 7, cq = idx % 7;                                \
                rb[it] = ((const float4*)(Wp + ((K0) + kr) * H1 + col0))[cq];  \
            }                                                                  \
        }                                                                      \
    }

#define STORE_TILE(BUF)                                                        \
    {                                                                          \
        _Pragma("unroll")                                                      \
        for (int it = 0; it < 5; it++) {                                       \
            int idx = tid + it * 128;                                          \
            if (idx < 576) {                                                   \
                int r = idx >> 3, kq = idx & 7;                                \
                As[BUF][kq * 4 + 0][r] = ra[it].x;                             \
                As[BUF][kq * 4 + 1][r] = ra[it].y;                             \
                As[BUF][kq * 4 + 2][r] = ra[it].z;                             \
                As[BUF][kq * 4 + 3][r] = ra[it].w;                             \
            }                                                                  \
        }                                                                      \
        _Pragma("unroll")                                                      \
        for (int it = 0; it < 2; it++) {                                       \
            int idx = tid + it * 128;                                          \
            if (idx < 224) { Bs[BUF][idx / 7][idx % 7] = rb[it]; }             \
        }                                                                      \
    }

    LOAD_TILE(0);
    STORE_TILE(0);
    __syncthreads();

    for (int kt = 0; kt < 16; kt++) {
        int cur = kt & 1;
        if (kt < 15) LOAD_TILE((kt + 1) * 32);
        if (active) {
#pragma unroll
            for (int kk = 0; kk < 32; kk++) {
                float a0 = As[cur][kk][ty * 4 + 0];
                float a1 = As[cur][kk][ty * 4 + 1];
                float a2 = As[cur][kk][ty * 4 + 2];
                float a3 = As[cur][kk][ty * 4 + 3];
                float4 b = Bs[cur][kk][tx];
                acc[0][0] += a0 * b.x; acc[0][1] += a0 * b.y; acc[0][2] += a0 * b.z; acc[0][3] += a0 * b.w;
                acc[1][0] += a1 * b.x; acc[1][1] += a1 * b.y; acc[1][2] += a1 * b.z; acc[1][3] += a1 * b.w;
                acc[2][0] += a2 * b.x; acc[2][1] += a2 * b.y; acc[2][2] += a2 * b.z; acc[2][3] += a2 * b.w;
                acc[3][0] += a3 * b.x; acc[3][1] += a3 * b.y; acc[3][2] += a3 * b.z; acc[3][3] += a3 * b.w;
            }
        }
        if (kt < 15) {
            STORE_TILE(cur ^ 1);
            __syncthreads();
        }
    }

    if (active) {
        int cb = col0 + tx * 4;
        float b0 = bias[cb + 0], b1 = bias[cb + 1], b2 = bias[cb + 2], b3 = bias[cb + 3];
#pragma unroll
        for (int i = 0; i < 4; i++) {
            int row = row_base + ty * 4 + i;
            float4 o;
            o.x = gelu_f(360.0f * acc[i][0] + b0);
            o.y = gelu_f(360.0f * acc[i][1] + b1);
            o.z = gelu_f(360.0f * acc[i][2] + b2);
            o.w = gelu_f(360.0f * acc[i][3] + b3);
            *(float4*)&g_h1row[row * H1 + cb] = o;
        }
    }
#undef LOAD_TILE
#undef STORE_TILE
}

// ---------------------------------------------------------------------------
// K3: full tail. grid = 40 blocks (one per classifier row r), 256 threads.
//   hsum2 (node-conv-2, x64 batch factor) -> gemm2+gelu -> cls1+gelu -> cls2
//   -> broadcast [40,10] block x64 into output [2560,10].
// prop2_W staged in dynamic smem (88KB).
// ---------------------------------------------------------------------------
__global__ __launch_bounds__(256) void k_tail(const float* __restrict__ W2,
                                              const float* __restrict__ b2p,
                                              const float* __restrict__ nc2w,
                                              const float* __restrict__ cw1,
                                              const float* __restrict__ cb1,
                                              const float* __restrict__ cw2,
                                              const float* __restrict__ cb2,
                                              float* __restrict__ out) {
    extern __shared__ float dynsm[];
    float* sW2 = dynsm;               // 784*28 = 21952 floats
    float* hs2 = dynsm + 21952;       // 3*784  = 2352 floats
    __shared__ float part[252];
    __shared__ float o2[84];
    __shared__ float hc[32];
    __shared__ float orow[10];

    const int r = blockIdx.x;
    const int tid = threadIdx.x;

    // stage prop2_W into smem
    const float4* W4 = (const float4*)W2;
    for (int i = tid; i < (H1 * H2) / 4; i += 256) ((float4*)sW2)[i] = W4[i];

    // hsum2 rows for s = 3r .. 3r+2 (uses h1row rows 9r .. 9r+8)
    for (int j = tid; j < 3 * H1; j += 256) {
        int sl = j / H1, f = j - sl * H1;
        int rowg = 9 * r + 3 * sl;
        float a = 0.f;
#pragma unroll
        for (int p = 0; p < 3; p++)
            a += g_h1row[(rowg + p) * H1 + f] * nc2w[p * H1 + f];
        hs2[j] = 64.0f * a;
    }
    __syncthreads();

    // gemm2: 84 outputs, 3 k-chunks each
    if (tid < 252) {
        int o = tid % 84, kg = tid / 84;
        int sl = o / 28, c = o - sl * 28;
        int k0 = kg * 262;
        int k1 = (kg == 2) ? H1 : k0 + 262;
        const float* hrow = hs2 + sl * H1;
        float a = 0.f;
        for (int k = k0; k < k1; k++) a += hrow[k] * sW2[k * H2 + c];
        part[kg * 84 + o] = a;
    }
    __syncthreads();
    if (tid < 84) {
        float s = part[tid] + part[84 + tid] + part[168 + tid];
        o2[tid] = gelu_f(120.0f * s + b2p[tid % 28]);
    }
    __syncthreads();

    // classifier layer 1: hc[j] = gelu(o2 . cw1[:,j] + cb1[j])
    if (tid < 32) {
        float a = cb1[tid];
#pragma unroll 4
        for (int k = 0; k < 84; k++) a += o2[k] * cw1[k * 32 + tid];
        hc[tid] = gelu_f(a);
    }
    __syncthreads();

    // classifier layer 2
    if (tid < 10) {
        float a = cb2[tid];
#pragma unroll
        for (int k = 0; k < 32; k++) a += hc[k] * cw2[k * 10 + tid];
        orow[tid] = a;
    }
    __syncthreads();

    // broadcast into output: out[(b*40 + r)*10 + c] for b = 0..63
    for (int i = tid; i < 640; i += 256) {
        int b = i / 10, c = i - b * 10;
        out[b * 400 + r * 10 + c] = orow[c];
    }
}

extern "C" void kernel_launch(void* const* d_in, const int* in_sizes, int n_in,
                              void* d_out, int out_size) {
    (void)in_sizes; (void)n_in; (void)out_size;
    const float* x       = (const float*)d_in[0];
    const float* nc1_w   = (const float*)d_in[1];
    // d_in[2]=gap1_w, d_in[3]=gap1_b : adjacency collapses to ~I -> irrelevant
    const float* prop1_W = (const float*)d_in[4];
    const float* prop1_b = (const float*)d_in[5];
    const float* nc2_w   = (const float*)d_in[6];
    // d_in[7]=gap2_w, d_in[8]=gap2_b : irrelevant
    const float* prop2_W = (const float*)d_in[9];
    const float* prop2_b = (const float*)d_in[10];
    const float* cls_w1  = (const float*)d_in[11];
    const float* cls_b1  = (const float*)d_in[12];
    const float* cls_w2  = (const float*)d_in[13];
    const float* cls_b2  = (const float*)d_in[14];
    float* out = (float*)d_out;

    // idempotent, host-side, not a stream op: safe under capture
    cudaFuncSetAttribute(k_tail, cudaFuncAttributeMaxDynamicSharedMemorySize, 98304);

    k_fuse1<<<dim3(180, 8), 256>>>((const float4*)x, (const float4*)nc1_w);
    k_reduce<<<180, 256>>>();
    k_gemm1<<<dim3(28, 5), 128>>>(prop1_W, prop1_b);
    k_tail<<<40, 256, (21952 + 2352) * sizeof(float)>>>(
        prop2_W, prop2_b, nc2_w, cls_w1, cls_b1, cls_w2, cls_b2, out);
}